// round 2
// baseline (speedup 1.0000x reference)
#include <cuda_runtime.h>
#include <cuda_fp16.h>

#define D     128
#define ROWS  128
#define TPB   256
#define SPT   132            // sPiT row stride (padded: 4k-offset banks, 16B aligned)
#define SVS   129            // sV   row stride (odd: spreads column-store banks)

// shared memory layout (floats)
#define OFF_PIT 0            // sPiT[k*SPT + j]   (reused as sV[j*SVS + r] after GEMM1)
#define OFF_PI  16896        // sPi [j*D   + k]
#define OFF_X   33280        // sX  [k*D   + r]   (x * invnorm, transposed)
#define OFF_NQ  49664        // sNq [r]
#define SMEM_FLOATS 49792    // 199,168 bytes

typedef unsigned long long ull;

union F4U { float4 f4; ull u[2]; float s[4]; };

__device__ __forceinline__ ull dup2(float v) {
    ull r; unsigned u = __float_as_uint(v);
    asm("mov.b64 %0, {%1, %1};" : "=l"(r) : "r"(u));
    return r;
}
__device__ __forceinline__ void ffma2(ull& d, ull a, ull b) {
    asm("fma.rn.f32x2 %0, %1, %2, %3;" : "=l"(d) : "l"(a), "l"(b), "l"(d));
}
__device__ __forceinline__ void fmul2(ull& d, ull a, ull b) {
    asm("mul.rn.f32x2 %0, %1, %2;" : "=l"(d) : "l"(a), "l"(b));
}
__device__ __forceinline__ void unpack2(ull v, float& a, float& b) {
    unsigned ua, ub;
    asm("mov.b64 {%0, %1}, %2;" : "=r"(ua), "=r"(ub) : "l"(v));
    a = __uint_as_float(ua); b = __uint_as_float(ub);
}

__global__ void __launch_bounds__(TPB, 1)
tq_kernel(const float* __restrict__ x, const float* __restrict__ Pi,
          const float* __restrict__ cen, const float* __restrict__ bnd,
          float* __restrict__ out)
{
    extern __shared__ float sm[];
    float* sPiT = sm + OFF_PIT;
    float* sV   = sm + OFF_PIT;   // overlays sPiT (dead after GEMM1)
    float* sPi  = sm + OFF_PI;
    float* sX   = sm + OFF_X;
    float* sNq  = sm + OFF_NQ;

    const int tid = threadIdx.x;

    // ---- codebook -> registers: interior boundaries + centroid deltas ----
    float B[15], Dl[15];
    const float c0 = cen[0];
    {
        float prev = c0;
#pragma unroll
        for (int i = 0; i < 15; i++) {
            B[i]  = bnd[i + 1];           // boundaries[1..15] (interior)
            float c = cen[i + 1];
            Dl[i] = c - prev;
            prev  = c;
        }
    }

    // ---- load Pi: row-major copy + padded transpose ----
#pragma unroll
    for (int i = 0; i < 16; i++) {
        int idx = tid + i * TPB;                 // float4 index over 4096
        ((float4*)sPi)[idx] = ((const float4*)Pi)[idx];
    }
#pragma unroll
    for (int i = 0; i < 64; i++) {
        int idx = tid + i * TPB;                 // scalar index over 16384
        int j = idx >> 7, k = idx & 127;
        sPiT[k * SPT + j] = Pi[idx];
    }

    // ---- load x tile, compute norms, store x*invn transposed [k][r] ----
    {
        const int r = tid >> 1, h = tid & 1;
        const float4* xr = (const float4*)(x + ((size_t)blockIdx.x * ROWS + r) * D + h * 64);
        float4 xv[16];
        float ss = 0.f;
#pragma unroll
        for (int i = 0; i < 16; i++) {
            xv[i] = xr[i];
            ss += xv[i].x * xv[i].x + xv[i].y * xv[i].y
                + xv[i].z * xv[i].z + xv[i].w * xv[i].w;
        }
        ss += __shfl_xor_sync(0xffffffffu, ss, 1);
        float norm = sqrtf(ss);
        float invn = 1.0f / (norm + 1e-8f);
        if (h == 0) sNq[r] = __half2float(__float2half(norm));  // fp16 round trip
#pragma unroll
        for (int i = 0; i < 16; i++) {
            int k0 = h * 64 + i * 4;
            sX[(k0    ) * D + r] = xv[i].x * invn;
            sX[(k0 + 1) * D + r] = xv[i].y * invn;
            sX[(k0 + 2) * D + r] = xv[i].z * invn;
            sX[(k0 + 3) * D + r] = xv[i].w * invn;
        }
    }
    __syncthreads();

    const int tx  = tid & 7;     // 8 col groups: cols {4*tx + 32*qb + c}
    const int ty  = tid >> 3;    // 32 row groups: rows {4*ty + p}
    const int r0  = ty * 4;
    const int cc0 = tx * 4;

    ull acc[4][8];
#pragma unroll
    for (int p = 0; p < 4; p++)
#pragma unroll
        for (int q = 0; q < 8; q++) acc[p][q] = 0ull;

    // ---- GEMM1: rotated[r][j] = sum_k sX[k][r] * PiT[k][j] ----
#pragma unroll 4
    for (int k = 0; k < D; k++) {
        F4U av; av.f4 = *(const float4*)(sX + k * D + r0);
        ull ad0 = dup2(av.s[0]), ad1 = dup2(av.s[1]),
            ad2 = dup2(av.s[2]), ad3 = dup2(av.s[3]);
        const float* pk = sPiT + k * SPT + cc0;
        F4U b0, b1, b2, b3;
        b0.f4 = *(const float4*)(pk);
        b1.f4 = *(const float4*)(pk + 32);
        b2.f4 = *(const float4*)(pk + 64);
        b3.f4 = *(const float4*)(pk + 96);
#pragma unroll
        for (int p = 0; p < 4; p++) {
            ull ad = (p == 0) ? ad0 : (p == 1) ? ad1 : (p == 2) ? ad2 : ad3;
            ffma2(acc[p][0], ad, b0.u[0]);
            ffma2(acc[p][1], ad, b0.u[1]);
            ffma2(acc[p][2], ad, b1.u[0]);
            ffma2(acc[p][3], ad, b1.u[1]);
            ffma2(acc[p][4], ad, b2.u[0]);
            ffma2(acc[p][5], ad, b2.u[1]);
            ffma2(acc[p][6], ad, b3.u[0]);
            ffma2(acc[p][7], ad, b3.u[1]);
        }
    }
    __syncthreads();   // all reads of sPiT / sX complete before sV overwrite

    // ---- quantize (Lloyd-Max bucketize, side='left') & store sV[j][r] ----
#pragma unroll
    for (int p = 0; p < 4; p++) {
#pragma unroll
        for (int q = 0; q < 8; q++) {
            int j0 = cc0 + (q >> 1) * 32 + (q & 1) * 2;
            float v0, v1;
            unpack2(acc[p][q], v0, v1);
            float w0 = c0, w1 = c0;
#pragma unroll
            for (int i = 0; i < 15; i++) {
                if (v0 > B[i]) w0 += Dl[i];
                if (v1 > B[i]) w1 += Dl[i];
            }
            sV[(j0    ) * SVS + (r0 + p)] = w0;
            sV[(j0 + 1) * SVS + (r0 + p)] = w1;
        }
    }
    __syncthreads();

    // ---- GEMM2: recon[r][k] = sum_j sV[j][r] * Pi[j][k] ----
#pragma unroll
    for (int p = 0; p < 4; p++)
#pragma unroll
        for (int q = 0; q < 8; q++) acc[p][q] = 0ull;

#pragma unroll 4
    for (int j = 0; j < D; j++) {
        const float* vj = sV + j * SVS + r0;
        ull ad0 = dup2(vj[0]), ad1 = dup2(vj[1]),
            ad2 = dup2(vj[2]), ad3 = dup2(vj[3]);
        const float* pj = sPi + j * D + cc0;
        F4U b0, b1, b2, b3;
        b0.f4 = *(const float4*)(pj);
        b1.f4 = *(const float4*)(pj + 32);
        b2.f4 = *(const float4*)(pj + 64);
        b3.f4 = *(const float4*)(pj + 96);
#pragma unroll
        for (int p = 0; p < 4; p++) {
            ull ad = (p == 0) ? ad0 : (p == 1) ? ad1 : (p == 2) ? ad2 : ad3;
            ffma2(acc[p][0], ad, b0.u[0]);
            ffma2(acc[p][1], ad, b0.u[1]);
            ffma2(acc[p][2], ad, b1.u[0]);
            ffma2(acc[p][3], ad, b1.u[1]);
            ffma2(acc[p][4], ad, b2.u[0]);
            ffma2(acc[p][5], ad, b2.u[1]);
            ffma2(acc[p][6], ad, b3.u[0]);
            ffma2(acc[p][7], ad, b3.u[1]);
        }
    }

    // ---- epilogue: scale by fp16-roundtripped norm, vectorized store ----
    const size_t obase = (size_t)blockIdx.x * ROWS * D;
#pragma unroll
    for (int p = 0; p < 4; p++) {
        ull nd = dup2(sNq[r0 + p]);
#pragma unroll
        for (int q = 0; q < 8; q++) fmul2(acc[p][q], acc[p][q], nd);
#pragma unroll
        for (int qb = 0; qb < 4; qb++) {
            F4U o;
            o.u[0] = acc[p][2 * qb];
            o.u[1] = acc[p][2 * qb + 1];
            *(float4*)(out + obase + (size_t)(r0 + p) * D + cc0 + 32 * qb) = o.f4;
        }
    }
}

extern "C" void kernel_launch(void* const* d_in, const int* in_sizes, int n_in,
                              void* d_out, int out_size)
{
    const float* x   = (const float*)d_in[0];
    const float* Pi  = (const float*)d_in[1];
    const float* cen = (const float*)d_in[2];
    const float* bnd = (const float*)d_in[3];
    float* out = (float*)d_out;

    const int n_rows = in_sizes[0] / D;        // 262144
    const int blocks = n_rows / ROWS;          // 2048

    const size_t smem = SMEM_FLOATS * sizeof(float);
    cudaFuncSetAttribute(tq_kernel, cudaFuncAttributeMaxDynamicSharedMemorySize, (int)smem);
    tq_kernel<<<blocks, TPB, smem>>>(x, Pi, cen, bnd, out);
}